// round 2
// baseline (speedup 1.0000x reference)
#include <cuda_runtime.h>
#include <math.h>

// Problem constants
#define T_LEN 32768
#define D_IN  512
#define H_DIM 1024
#define S_DIM 256
#define G3    (3 * H_DIM)   // 3072

// Scan configuration: 128 persistent CTAs, 8 h-outputs per CTA, 24 w_hh rows per CTA.
#define NC           128
#define JPC          (H_DIM / NC)        // 8
#define SCAN_THREADS 256                 // 8 warps, 3 rows per warp

// -------- Scratch (device globals; no dynamic allocation allowed) ----------
__device__ float g_igates[(size_t)T_LEN * G3];   // ~403 MB
__device__ float g_hs[(size_t)T_LEN * H_DIM];    // ~134 MB
__device__ float g_h[2][H_DIM];                  // ping-pong hidden state
__device__ unsigned g_bar_count;
__device__ volatile unsigned g_bar_gen;

// ---------------------------------------------------------------------------
// Init: h = tanh(h0); reset barrier state (runs every replay).
// ---------------------------------------------------------------------------
__global__ void init_kernel(const float* __restrict__ h0)
{
    int i = threadIdx.x;
    if (i < H_DIM) g_h[0][i] = tanhf(h0[i]);
    if (i == 0) { g_bar_count = 0u; g_bar_gen = 0u; }
}

// ---------------------------------------------------------------------------
// Tiled fp32 GEMM:  C[m][n] = sum_k A[m][k] * B[n][k] + bias[n]
//   A row-major [M,K], B row-major [N,K] ("NT" layout, both K-contiguous).
//   mode 0: A = param (y),  C = g_igates                      (igates GEMM)
//   mode 1: A = g_hs,       C = d_out split + softplus epilogue (output GEMM)
//
// Tiles: 128x128x16, 256 threads. Warp tile 32x64; lane = (r=lane>>3, c=lane&7).
// Thread owns rows {r*4+0..3, r*4+16..19}, cols {c*4+0..3, c*4+32..35} within
// the warp tile -> all smem fragment reads are float4 at lane-stride-4 words:
// A-frags broadcast within an 8-lane phase, B-frags span all 32 banks.
// Conflict-free by construction.
// ---------------------------------------------------------------------------
__global__ __launch_bounds__(256) void gemm_kernel(
    const float* __restrict__ Ain,
    const float* __restrict__ Bm,
    const float* __restrict__ bias,
    float* __restrict__ Cout,
    int M, int N, int K, int mode)
{
    __shared__ float As[16][128];
    __shared__ float Bs[16][128];

    const float* A = (mode == 0) ? Ain : g_hs;

    int bm = blockIdx.y;
    int bn = blockIdx.x;
    int tid  = threadIdx.x;
    int warp = tid >> 5;
    int lane = tid & 31;
    int wy = warp >> 1;          // 0..3  -> warp row (32 rows each)
    int wx = warp & 1;           // 0..1  -> warp col (64 cols each)
    int r  = lane >> 3;          // 0..3
    int c  = lane & 7;           // 0..7

    const float* Ab = A  + (size_t)bm * 128 * K;
    const float* Bb = Bm + (size_t)bn * 128 * K;

    float acc[2][4][2][4];
#pragma unroll
    for (int ia = 0; ia < 2; ia++)
#pragma unroll
        for (int i = 0; i < 4; i++)
#pragma unroll
            for (int jb = 0; jb < 2; jb++)
#pragma unroll
                for (int j = 0; j < 4; j++) acc[ia][i][jb][j] = 0.f;

    for (int kt = 0; kt < K; kt += 16) {
        // Each thread loads 2 float4 of A and 2 float4 of B, stores transposed.
#pragma unroll
        for (int s = 0; s < 2; s++) {
            int idx = tid * 2 + s;          // 0..511
            int row = idx >> 2;             // 0..127
            int k4  = idx & 3;              // 0..3
            float4 va = *(const float4*)(Ab + (size_t)row * K + kt + k4 * 4);
            As[k4 * 4 + 0][row] = va.x;
            As[k4 * 4 + 1][row] = va.y;
            As[k4 * 4 + 2][row] = va.z;
            As[k4 * 4 + 3][row] = va.w;
            float4 vb = *(const float4*)(Bb + (size_t)row * K + kt + k4 * 4);
            Bs[k4 * 4 + 0][row] = vb.x;
            Bs[k4 * 4 + 1][row] = vb.y;
            Bs[k4 * 4 + 2][row] = vb.z;
            Bs[k4 * 4 + 3][row] = vb.w;
        }
        __syncthreads();

#pragma unroll
        for (int kk = 0; kk < 16; kk++) {
            float4 a0 = *(const float4*)&As[kk][wy * 32 + r * 4];
            float4 a1 = *(const float4*)&As[kk][wy * 32 + r * 4 + 16];
            float4 b0 = *(const float4*)&Bs[kk][wx * 64 + c * 4];
            float4 b1 = *(const float4*)&Bs[kk][wx * 64 + c * 4 + 32];
            float av[2][4] = {{a0.x, a0.y, a0.z, a0.w}, {a1.x, a1.y, a1.z, a1.w}};
            float bv[2][4] = {{b0.x, b0.y, b0.z, b0.w}, {b1.x, b1.y, b1.z, b1.w}};
#pragma unroll
            for (int ia = 0; ia < 2; ia++)
#pragma unroll
                for (int i = 0; i < 4; i++)
#pragma unroll
                    for (int jb = 0; jb < 2; jb++)
#pragma unroll
                        for (int j = 0; j < 4; j++)
                            acc[ia][i][jb][j] += av[ia][i] * bv[jb][j];
        }
        __syncthreads();
    }

    // Epilogue
#pragma unroll
    for (int ia = 0; ia < 2; ia++) {
#pragma unroll
        for (int i = 0; i < 4; i++) {
            int m = bm * 128 + wy * 32 + r * 4 + ia * 16 + i;
#pragma unroll
            for (int jb = 0; jb < 2; jb++) {
#pragma unroll
                for (int j = 0; j < 4; j++) {
                    int n = bn * 128 + wx * 64 + c * 4 + jb * 32 + j;
                    float v = acc[ia][i][jb][j] + bias[n];
                    if (mode == 0) {
                        g_igates[(size_t)m * G3 + n] = v;
                    } else {
                        if (n < S_DIM) {
                            Cout[(size_t)m * S_DIM + n] = v;             // nat1
                        } else {
                            // softplus, stable: max(x,0)+log1p(exp(-|x|))
                            float sp = fmaxf(v, 0.f) + log1pf(expf(-fabsf(v)));
                            Cout[(size_t)T_LEN * S_DIM + (size_t)m * S_DIM + (n - S_DIM)] = sp;
                        }
                    }
                }
            }
        }
    }
}

// ---------------------------------------------------------------------------
// Persistent GRU scan.
//   128 CTAs x 256 threads. CTA c owns h-indices [8c, 8c+8).
//   24 w_hh rows per CTA held in registers (float4 w[3][8] per lane).
//   h is staged ONCE per CTA into smem (coalesced 4KB ldg), then all warps
//   read it via conflict-free LDS.128 (lane stride 4 words).
//   Per step: chip-wide barrier (atomic counter + volatile gen word in L2).
// ---------------------------------------------------------------------------
__global__ __launch_bounds__(SCAN_THREADS, 1) void scan_kernel(
    const float* __restrict__ w_hh,
    const float* __restrict__ bn_vec)
{
    int c    = blockIdx.x;
    int tid  = threadIdx.x;
    int warp = tid >> 5;
    int lane = tid & 31;

    // --- Load this CTA's weight slice into registers --------------------
    // lr = warp*3+rr enumerates 0..23; (gate, joff) = (lr>>3, lr&7); lr == gate*8+joff.
    float4 w[3][8];
#pragma unroll
    for (int rr = 0; rr < 3; rr++) {
        int lr   = warp * 3 + rr;                       // 0..23
        int grow = (lr >> 3) * H_DIM + c * JPC + (lr & 7);
        const float* wr = w_hh + (size_t)grow * H_DIM;
#pragma unroll
        for (int i = 0; i < 8; i++)
            w[rr][i] = *(const float4*)(wr + i * 128 + lane * 4);
    }

    float bnv = (tid < JPC) ? bn_vec[c * JPC + tid] : 0.f;

    __shared__ float4 hsm4[H_DIM / 4];   // staged h, 4KB
    __shared__ float  red[24];
    __shared__ float  igs[24];

    for (int t = 0; t < T_LEN; t++) {
        const float* hb = g_h[t & 1];

        // Prefetch input gates for this CTA (L2/DRAM, consumed late).
        float ig = 0.f;
        if (tid < 24) {
            int gate = tid >> 3, joff = tid & 7;
            ig = __ldcg(&g_igates[(size_t)t * G3 + gate * H_DIM + c * JPC + joff]);
        }

        // Stage full h (4KB) into smem: one coalesced float4 per thread, .cg
        // to bypass stale L1 (written by other SMs last step).
        hsm4[tid] = __ldcg((const float4*)hb + tid);
        __syncthreads();

        float hprev = (tid < JPC) ? ((const float*)hsm4)[c * JPC + tid] : 0.f;

        // 3 dot-products of length 1024 per warp (32 elems/lane each).
        float acc0 = 0.f, acc1 = 0.f, acc2 = 0.f;
#pragma unroll
        for (int i = 0; i < 8; i++) {
            float4 h4 = hsm4[i * 32 + lane];
            acc0 += w[0][i].x * h4.x + w[0][i].y * h4.y
                  + w[0][i].z * h4.z + w[0][i].w * h4.w;
            acc1 += w[1][i].x * h4.x + w[1][i].y * h4.y
                  + w[1][i].z * h4.z + w[1][i].w * h4.w;
            acc2 += w[2][i].x * h4.x + w[2][i].y * h4.y
                  + w[2][i].z * h4.z + w[2][i].w * h4.w;
        }
#pragma unroll
        for (int off = 16; off > 0; off >>= 1) {
            acc0 += __shfl_xor_sync(0xffffffffu, acc0, off);
            acc1 += __shfl_xor_sync(0xffffffffu, acc1, off);
            acc2 += __shfl_xor_sync(0xffffffffu, acc2, off);
        }
        if (lane == 0) {
            red[warp * 3 + 0] = acc0;
            red[warp * 3 + 1] = acc1;
            red[warp * 3 + 2] = acc2;
        }
        if (tid < 24) igs[tid] = ig;
        __syncthreads();

        // Gate math for this CTA's 8 hidden units.
        if (tid < JPC) {
            float hrv = red[tid], hzv = red[8 + tid], hnv = red[16 + tid];
            float irv = igs[tid], izv = igs[8 + tid], innv = igs[16 + tid];
            float r = 1.f / (1.f + expf(-(irv + hrv)));
            float z = 1.f / (1.f + expf(-(izv + hzv)));
            float n = tanhf(innv + r * (hnv + bnv));
            float hnew = n + z * (hprev - n);
            g_h[(t + 1) & 1][c * JPC + tid] = hnew;
            g_hs[(size_t)t * H_DIM + c * JPC + tid] = hnew;
        }
        __syncthreads();

        // ---- Chip-wide barrier (release/acquire via L2) ----------------
        // Cumulative fence by t0 after __syncthreads covers the CTA's stores.
        if (tid == 0) {
            __threadfence();                         // release h writes
            unsigned arr    = atomicAdd(&g_bar_count, 1u);
            unsigned target = (unsigned)NC * (unsigned)(t + 1);
            if (arr == target - 1u) {
                g_bar_gen = target;                  // volatile store
            } else {
                while (g_bar_gen < target) { }       // volatile spin
            }
            __threadfence();                         // acquire
        }
        __syncthreads();
    }
}

// ---------------------------------------------------------------------------
extern "C" void kernel_launch(void* const* d_in, const int* in_sizes, int n_in,
                              void* d_out, int out_size)
{
    const float* y     = (const float*)d_in[0];  // [T, D]
    const float* h0    = (const float*)d_in[1];  // [H]
    const float* w_ih  = (const float*)d_in[2];  // [3H, D]
    const float* w_hh  = (const float*)d_in[3];  // [3H, H]
    const float* b     = (const float*)d_in[4];  // [3H]
    const float* bn    = (const float*)d_in[5];  // [H]
    const float* w_out = (const float*)d_in[6];  // [2S, H]
    const float* b_out = (const float*)d_in[7];  // [2S]
    float* out = (float*)d_out;                  // [T*S nat1][T*S softplus(nat2)]

    // 1) init h + barrier state
    init_kernel<<<1, 1024>>>(h0);

    // 2) igates = y @ w_ih.T + b   -> g_igates  [T, 3H]
    {
        dim3 grid(G3 / 128, T_LEN / 128);
        gemm_kernel<<<grid, 256>>>(y, w_ih, b, nullptr, T_LEN, G3, D_IN, 0);
    }

    // 3) sequential GRU scan -> g_hs [T, H]
    scan_kernel<<<NC, SCAN_THREADS>>>(w_hh, bn);

    // 4) out = hs @ w_out.T + b_out; split + softplus -> d_out
    {
        dim3 grid((2 * S_DIM) / 128, T_LEN / 128);
        gemm_kernel<<<grid, 256>>>(nullptr, w_out, b_out, out, T_LEN, 2 * S_DIM, H_DIM, 1);
    }
}